// round 4
// baseline (speedup 1.0000x reference)
#include <cuda_runtime.h>

#define THREADS 512
#define TB 32          // batch elements per CTA
#define MROWS 96       // token rows per CTA (TB*3)
#define LDA 104        // smem row stride for activations (float4-aligned)
#define DM 100
#define DIN 72
#define FFD 512
#define FC 64          // FFN chunk
#define NLAYERS 8
#define NCLS 40
#define SD 300

#define OFF_X 0
#define OFF_Q 9984
#define OFF_K 19968
#define OFF_V 29952
#define OFF_W 39936
#define SMEM_FLOATS 52096   // 208,384 bytes dynamic smem

#define SW_LDW 108      // weight stride for K<=100 staged blocks (x4-aligned, conflict-free)
#define SW2_LDW 68      // weight stride for FC-col blocks
#define WF_LDW 304      // classifier weight stride (float2-aligned)

typedef unsigned long long ull;

__device__ __forceinline__ void ffma2(ull& acc, ull a, ull b) {
  asm("fma.rn.f32x2 %0, %1, %2, %0;" : "+l"(acc) : "l"(a), "l"(b));
}
__device__ __forceinline__ ull pack2(float x, float y) {
  ull r; asm("mov.b64 %0, {%1, %2};" : "=l"(r) : "f"(x), "f"(y)); return r;
}
__device__ __forceinline__ float sum2(ull v) {
  float lo, hi; asm("mov.b64 {%0, %1}, %2;" : "=f"(lo), "=f"(hi) : "l"(v));
  return lo + hi;
}

// Copy weight block (row-major [rows x cols]) into shared with row stride ldw,
// zero-padding rows up to prows.
__device__ __forceinline__ void stage_w(float* dst, int ldw, const float* __restrict__ src,
                                        int sstride, int rows, int cols, int prows) {
  const int total = prows * cols;
  for (int idx = threadIdx.x; idx < total; idx += THREADS) {
    int r = idx / cols;
    int c = idx - r * cols;
    dst[r * ldw + c] = (r < rows) ? src[r * sstride + c] : 0.0f;
  }
}

// C[m][n] += sum_k A[m][k] * W[n][k]
// 512 threads as 32(tm) x 16(tn); each thread owns rows {tm, tm+32, tm+64},
// cols {tn, tn+16, ...}. f32x2 packed accumulation, float4 shared loads.
template <int NC>
__device__ __forceinline__ void gemm_acc2(const float* __restrict__ A, int lda,
                                          const float* __restrict__ W, int ldw,
                                          int K, ull (&acc)[3][NC]) {
  const int tn = threadIdx.x & 15;
  const int tm = threadIdx.x >> 4;
  const float* a0 = A + tm * lda;
  const float* w0 = W + tn * ldw;
#pragma unroll 2
  for (int k = 0; k < K; k += 4) {
    float4 a4[3];
#pragma unroll
    for (int r = 0; r < 3; r++)
      a4[r] = *reinterpret_cast<const float4*>(a0 + r * 32 * lda + k);
    ull alo[3], ahi[3];
#pragma unroll
    for (int r = 0; r < 3; r++) { alo[r] = pack2(a4[r].x, a4[r].y); ahi[r] = pack2(a4[r].z, a4[r].w); }
#pragma unroll
    for (int c = 0; c < NC; c++) {
      float4 w4 = *reinterpret_cast<const float4*>(w0 + c * 16 * ldw + k);
      ull wlo = pack2(w4.x, w4.y), whi = pack2(w4.z, w4.w);
#pragma unroll
      for (int r = 0; r < 3; r++) {
        ffma2(acc[r][c], alo[r], wlo);
        ffma2(acc[r][c], ahi[r], whi);
      }
    }
  }
}

template <int NC>
__device__ __forceinline__ void zero_acc(ull (&acc)[3][NC]) {
#pragma unroll
  for (int r = 0; r < 3; r++)
#pragma unroll
    for (int c = 0; c < NC; c++) acc[r][c] = 0ull;
}

__device__ __forceinline__ void layernorm_rows(const float* __restrict__ src,
                                               float* __restrict__ dst,
                                               const float* __restrict__ g,
                                               const float* __restrict__ b) {
  const int tid = threadIdx.x;
  if (tid < MROWS) {
    const float* y = src + tid * LDA;
    float m = 0.f;
#pragma unroll 4
    for (int d = 0; d < DM; d++) m += y[d];
    m *= (1.0f / DM);
    float v = 0.f;
#pragma unroll 4
    for (int d = 0; d < DM; d++) { float t = y[d] - m; v = fmaf(t, t, v); }
    v *= (1.0f / DM);
    float inv = rsqrtf(v + 1e-5f);
    float* o = dst + tid * LDA;
#pragma unroll 4
    for (int d = 0; d < DM; d++)
      o[d] = (y[d] - m) * inv * __ldg(g + d) + __ldg(b + d);
  }
}

__global__ void __launch_bounds__(THREADS, 1)
geomapnet_kernel(const float* __restrict__ x,
                 const float* __restrict__ We, const float* __restrict__ be,
                 const float* __restrict__ pe,
                 const float* __restrict__ Wq, const float* __restrict__ bq,
                 const float* __restrict__ Wk, const float* __restrict__ bk,
                 const float* __restrict__ Wv, const float* __restrict__ bv,
                 const float* __restrict__ Wo, const float* __restrict__ bo,
                 const float* __restrict__ ln1g, const float* __restrict__ ln1b,
                 const float* __restrict__ W1, const float* __restrict__ b1,
                 const float* __restrict__ W2, const float* __restrict__ b2,
                 const float* __restrict__ ln2g, const float* __restrict__ ln2b,
                 const float* __restrict__ Wf, const float* __restrict__ bf,
                 float* __restrict__ out)
{
  extern __shared__ float smem[];
  float* sX = smem + OFF_X;   // [96][104] residual-stream activations
  float* sQ = smem + OFF_Q;   // [96][104] Q / ctx / FFN hidden chunk
  float* sK = smem + OFF_K;   // [96][104] K / pre-LN scratch
  float* sV = smem + OFF_V;   // [96][104] V
  float* sW = smem + OFF_W;   // weight staging, 12160 floats

  const int tid = threadIdx.x;
  const int tn = tid & 15;
  const int tm = tid >> 4;
  const int rowbase = blockIdx.x * MROWS;

  // ---------------- embedding: X = x @ We^T + be + pe ----------------
  for (int idx = tid; idx < MROWS * DIN; idx += THREADS) {
    int r = idx / DIN, c = idx - r * DIN;
    sQ[r * LDA + c] = x[(rowbase + r) * DIN + c];
  }
  stage_w(sW, SW_LDW, We, DIN, DM, DIN, 112);
  __syncthreads();
  {
    ull acc[3][7];
    zero_acc<7>(acc);
    gemm_acc2<7>(sQ, LDA, sW, SW_LDW, DIN, acc);
#pragma unroll
    for (int c = 0; c < 7; c++) {
      int n = tn + 16 * c;
      if (n < DM) {
        float bias = __ldg(be + n);
#pragma unroll
        for (int r = 0; r < 3; r++) {
          int m = tm + 32 * r;
          sX[m * LDA + n] = sum2(acc[r][c]) + bias + __ldg(pe + (m % 3) * DM + n);
        }
      }
    }
  }
  __syncthreads();

  // ---------------- encoder layers ----------------
  for (int li = 0; li < NLAYERS; li++) {
    const float* Wq_i = Wq + li * DM * DM;
    const float* Wk_i = Wk + li * DM * DM;
    const float* Wv_i = Wv + li * DM * DM;
    const float* Wo_i = Wo + li * DM * DM;
    const float* bq_i = bq + li * DM;
    const float* bk_i = bk + li * DM;
    const float* bv_i = bv + li * DM;
    const float* bo_i = bo + li * DM;

    // ---- Q projection ----
    stage_w(sW, SW_LDW, Wq_i, DM, DM, DM, 112);
    __syncthreads();
    {
      ull acc[3][7];
      zero_acc<7>(acc);
      gemm_acc2<7>(sX, LDA, sW, SW_LDW, DM, acc);
#pragma unroll
      for (int c = 0; c < 7; c++) {
        int n = tn + 16 * c;
        if (n < DM) {
          float bias = __ldg(bq_i + n);
#pragma unroll
          for (int r = 0; r < 3; r++) sQ[(tm + 32 * r) * LDA + n] = sum2(acc[r][c]) + bias;
        }
      }
    }
    __syncthreads();

    // ---- K projection ----
    stage_w(sW, SW_LDW, Wk_i, DM, DM, DM, 112);
    __syncthreads();
    {
      ull acc[3][7];
      zero_acc<7>(acc);
      gemm_acc2<7>(sX, LDA, sW, SW_LDW, DM, acc);
#pragma unroll
      for (int c = 0; c < 7; c++) {
        int n = tn + 16 * c;
        if (n < DM) {
          float bias = __ldg(bk_i + n);
#pragma unroll
          for (int r = 0; r < 3; r++) sK[(tm + 32 * r) * LDA + n] = sum2(acc[r][c]) + bias;
        }
      }
    }
    __syncthreads();

    // ---- V projection ----
    stage_w(sW, SW_LDW, Wv_i, DM, DM, DM, 112);
    __syncthreads();
    {
      ull acc[3][7];
      zero_acc<7>(acc);
      gemm_acc2<7>(sX, LDA, sW, SW_LDW, DM, acc);
#pragma unroll
      for (int c = 0; c < 7; c++) {
        int n = tn + 16 * c;
        if (n < DM) {
          float bias = __ldg(bv_i + n);
#pragma unroll
          for (int r = 0; r < 3; r++) sV[(tm + 32 * r) * LDA + n] = sum2(acc[r][c]) + bias;
        }
      }
    }
    __syncthreads();

    // ---- attention (flat row-major head split: head h = flat[h*30 .. h*30+30)) ----
    for (int task = tid; task < TB * 10; task += THREADS) {
      int e = task / 10;
      int h = task - e * 10;
      const int base = h * 30;
      const float* Qe = sQ + (3 * e) * LDA;
      const float* Ke = sK + (3 * e) * LDA;
      const float* Ve = sV + (3 * e) * LDA;
      // flat index f -> smem offset
      auto offf = [&](int f) { int s = f / 100; return s * LDA + (f - s * 100); };
      const float scale = 0.3162277660168379f;  // 10^-0.5
      // scores: q held per row, k streamed
      float att[3][3];
      float q[30];
#pragma unroll
      for (int j = 0; j < 30; j++) q[j] = Qe[offf(base + j)];
#pragma unroll
      for (int b2 = 0; b2 < 3; b2++) {
        float kk[10];
#pragma unroll
        for (int d3 = 0; d3 < 10; d3++) kk[d3] = Ke[offf(base + b2 * 10 + d3)];
#pragma unroll
        for (int a2 = 0; a2 < 3; a2++) {
          float s2 = 0.f;
#pragma unroll
          for (int d3 = 0; d3 < 10; d3++) s2 = fmaf(q[a2 * 10 + d3], kk[d3], s2);
          att[a2][b2] = s2 * scale;
        }
      }
#pragma unroll
      for (int a2 = 0; a2 < 3; a2++) {
        float mx = fmaxf(att[a2][0], fmaxf(att[a2][1], att[a2][2]));
        float sum = 0.f;
#pragma unroll
        for (int b2 = 0; b2 < 3; b2++) { att[a2][b2] = __expf(att[a2][b2] - mx); sum += att[a2][b2]; }
        float inv = 1.f / sum;
#pragma unroll
        for (int b2 = 0; b2 < 3; b2++) att[a2][b2] *= inv;
      }
      float* Qw = sQ + (3 * e) * LDA;
#pragma unroll
      for (int d3 = 0; d3 < 10; d3++) {
        float v0 = Ve[offf(base + d3)];
        float v1 = Ve[offf(base + 10 + d3)];
        float v2 = Ve[offf(base + 20 + d3)];
#pragma unroll
        for (int a2 = 0; a2 < 3; a2++) {
          float s2 = att[a2][0] * v0 + att[a2][1] * v1 + att[a2][2] * v2;
          Qw[offf(base + a2 * 10 + d3)] = s2;
        }
      }
    }
    __syncthreads();

    // ---- O projection + residual -> sK ----
    stage_w(sW, SW_LDW, Wo_i, DM, DM, DM, 112);
    __syncthreads();
    {
      ull acc[3][7];
      zero_acc<7>(acc);
      gemm_acc2<7>(sQ, LDA, sW, SW_LDW, DM, acc);
#pragma unroll
      for (int c = 0; c < 7; c++) {
        int n = tn + 16 * c;
        if (n < DM) {
          float bias = __ldg(bo_i + n);
#pragma unroll
          for (int r = 0; r < 3; r++) {
            int m = tm + 32 * r;
            sK[m * LDA + n] = sum2(acc[r][c]) + bias + sX[m * LDA + n];
          }
        }
      }
    }
    __syncthreads();

    // ---- LayerNorm 1 -> sX ----
    layernorm_rows(sK, sX, ln1g + li * DM, ln1b + li * DM);
    __syncthreads();

    // ---- FFN: y = relu(X@W1^T + b1) @ W2^T, chunked over FF ----
    ull yacc[3][7];
    zero_acc<7>(yacc);

    for (int cc = 0; cc < FFD / FC; cc++) {
      // stage W1 chunk [FC][DM]
      stage_w(sW, SW_LDW, W1 + (size_t)li * FFD * DM + cc * FC * DM, DM, FC, DM, FC);
      __syncthreads();
      {
        ull hacc[3][4];
        zero_acc<4>(hacc);
        gemm_acc2<4>(sX, LDA, sW, SW_LDW, DM, hacc);
        const float* b1c = b1 + li * FFD + cc * FC;
#pragma unroll
        for (int c = 0; c < 4; c++) {
          int n = tn + 16 * c;
          float bias = __ldg(b1c + n);
#pragma unroll
          for (int r = 0; r < 3; r++)
            sQ[(tm + 32 * r) * LDA + n] = fmaxf(sum2(hacc[r][c]) + bias, 0.f);
        }
      }
      __syncthreads();
      // stage W2 chunk: sW[d][ffl] = W2[d][cc*FC + ffl]
      stage_w(sW, SW2_LDW, W2 + (size_t)li * DM * FFD + cc * FC, FFD, DM, FC, 112);
      __syncthreads();
      gemm_acc2<7>(sQ, LDA, sW, SW2_LDW, FC, yacc);
      __syncthreads();
    }

    // ---- FFN bias + residual -> sK, then LayerNorm 2 -> sX ----
    {
      const float* b2i = b2 + li * DM;
#pragma unroll
      for (int c = 0; c < 7; c++) {
        int n = tn + 16 * c;
        if (n < DM) {
          float bias = __ldg(b2i + n);
#pragma unroll
          for (int r = 0; r < 3; r++) {
            int m = tm + 32 * r;
            sK[m * LDA + n] = sum2(yacc[r][c]) + bias + sX[m * LDA + n];
          }
        }
      }
    }
    __syncthreads();
    layernorm_rows(sK, sX, ln2g + li * DM, ln2b + li * DM);
    __syncthreads();
  }

  // ---------------- classifier: out = flat(X)[300] @ Wf^T + bf ----------------
  stage_w(sW, WF_LDW, Wf, SD, NCLS, SD, NCLS);
  __syncthreads();
  for (int task = tid; task < TB * NCLS; task += THREADS) {
    int e = task / NCLS;
    int c = task - e * NCLS;
    const float* Xe = sX + 3 * e * LDA;
    const float* wr = sW + c * WF_LDW;
    ull acc = 0ull;
#pragma unroll
    for (int s = 0; s < 3; s++) {
#pragma unroll 5
      for (int d = 0; d < DM; d += 2) {
        ffma2(acc, pack2(Xe[s * LDA + d], Xe[s * LDA + d + 1]),
                   pack2(wr[s * DM + d], wr[s * DM + d + 1]));
      }
    }
    out[(blockIdx.x * TB + e) * NCLS + c] = sum2(acc) + __ldg(bf + c);
  }
}

extern "C" void kernel_launch(void* const* d_in, const int* in_sizes, int n_in,
                              void* d_out, int out_size) {
  const float* x   = (const float*)d_in[0];
  // d_in[1] = label, d_in[2] = fa_label : unused by the forward pass
  const float* We  = (const float*)d_in[3];
  const float* be  = (const float*)d_in[4];
  const float* pe  = (const float*)d_in[5];
  const float* Wq  = (const float*)d_in[6];
  const float* bq  = (const float*)d_in[7];
  const float* Wk  = (const float*)d_in[8];
  const float* bk  = (const float*)d_in[9];
  const float* Wv  = (const float*)d_in[10];
  const float* bv  = (const float*)d_in[11];
  const float* Wo  = (const float*)d_in[12];
  const float* bo  = (const float*)d_in[13];
  const float* l1g = (const float*)d_in[14];
  const float* l1b = (const float*)d_in[15];
  const float* W1  = (const float*)d_in[16];
  const float* b1  = (const float*)d_in[17];
  const float* W2  = (const float*)d_in[18];
  const float* b2  = (const float*)d_in[19];
  const float* l2g = (const float*)d_in[20];
  const float* l2b = (const float*)d_in[21];
  const float* Wf  = (const float*)d_in[22];
  const float* bf  = (const float*)d_in[23];
  float* out = (float*)d_out;

  int Bsz = in_sizes[0] / (3 * DIN);       // 65536
  int nblocks = Bsz / TB;                  // 2048
  size_t smem = (size_t)SMEM_FLOATS * sizeof(float);  // 208,384 B

  cudaFuncSetAttribute(geomapnet_kernel,
                       cudaFuncAttributeMaxDynamicSharedMemorySize, (int)smem);
  geomapnet_kernel<<<nblocks, THREADS, smem>>>(x, We, be, pe, Wq, bq, Wk, bk, Wv, bv,
                                               Wo, bo, l1g, l1b, W1, b1, W2, b2,
                                               l2g, l2b, Wf, bf, out);
}

// round 6
// speedup vs baseline: 1.0028x; 1.0028x over previous
#include <cuda_runtime.h>

#define THREADS 512
#define TB 32
#define MROWS 96
#define LDA 104
#define DM 100
#define DIN 72
#define FFD 512
#define NLAYERS 8
#define NCLS 40
#define SD 300

// smem float offsets
#define OFF_X 0
#define OFF_Q 9984
#define OFF_K 19968
#define OFF_V 29952
#define OFF_W0 39936
#define OFF_W1 47552
#define BUFSZ 7616
#define SMEM_FLOATS 55168   // 220,672 bytes

#define QK_LDW 108   // QKV/O + W1 chunks: [64][108]
#define W2_LDW 68    // W2 chunks: [112][68]
#define WE_LDW 76    // embedding: [112][76] in combined region
#define WF_LDW 301   // classifier: [40][301] in combined region

typedef unsigned long long ull;

__device__ __forceinline__ void ffma2(ull& acc, ull a, ull b) {
  asm("fma.rn.f32x2 %0, %1, %2, %0;" : "+l"(acc) : "l"(a), "l"(b));
}
__device__ __forceinline__ ull pack2(float x, float y) {
  ull r; asm("mov.b64 %0, {%1, %2};" : "=l"(r) : "f"(x), "f"(y)); return r;
}
__device__ __forceinline__ float sum2(ull v) {
  float lo, hi; asm("mov.b64 {%0, %1}, %2;" : "=f"(lo), "=f"(hi) : "l"(v));
  return lo + hi;
}

// Copy weight block (row-major [rows x cols]) into shared with row stride ldw,
// zero-padding rows up to prows.
__device__ __forceinline__ void stage_w(float* dst, int ldw, const float* __restrict__ src,
                                        int sstride, int rows, int cols, int prows) {
  const int total = prows * cols;
  for (int idx = threadIdx.x; idx < total; idx += THREADS) {
    int r = idx / cols;
    int c = idx - r * cols;
    dst[r * ldw + c] = (r < rows) ? __ldg(src + r * sstride + c) : 0.0f;
  }
}

// C[m][n] += sum_k A[m][k] * W[n][k]
// 512 threads: 32(tm) x 16(tn); rows {tm, tm+32, tm+64}, cols {tn, tn+16,...}
template <int NC>
__device__ __forceinline__ void gemm_acc2(const float* __restrict__ A, int lda,
                                          const float* __restrict__ W, int ldw,
                                          int K, ull (&acc)[3][NC]) {
  const int tn = threadIdx.x & 15;
  const int tm = threadIdx.x >> 4;
  const float* a0 = A + tm * lda;
  const float* w0 = W + tn * ldw;
#pragma unroll 2
  for (int k = 0; k < K; k += 4) {
    float4 a4[3];
#pragma unroll
    for (int r = 0; r < 3; r++)
      a4[r] = *reinterpret_cast<const float4*>(a0 + r * 32 * lda + k);
    ull alo[3], ahi[3];
#pragma unroll
    for (int r = 0; r < 3; r++) { alo[r] = pack2(a4[r].x, a4[r].y); ahi[r] = pack2(a4[r].z, a4[r].w); }
#pragma unroll
    for (int c = 0; c < NC; c++) {
      float4 w4 = *reinterpret_cast<const float4*>(w0 + c * 16 * ldw + k);
      ull wlo = pack2(w4.x, w4.y), whi = pack2(w4.z, w4.w);
#pragma unroll
      for (int r = 0; r < 3; r++) {
        ffma2(acc[r][c], alo[r], wlo);
        ffma2(acc[r][c], ahi[r], whi);
      }
    }
  }
}

template <int NC>
__device__ __forceinline__ void zero_acc(ull (&acc)[3][NC]) {
#pragma unroll
  for (int r = 0; r < 3; r++)
#pragma unroll
    for (int c = 0; c < NC; c++) acc[r][c] = 0ull;
}

// epilogue for a 64-wide N chunk: dst[row][base+n] = acc + bias[base+n] (+resid)
__device__ __forceinline__ void epi4(ull (&acc)[3][4], int base,
                                     const float* __restrict__ bias,
                                     float* __restrict__ dst,
                                     const float* __restrict__ resid) {
  const int tn = threadIdx.x & 15;
  const int tm = threadIdx.x >> 4;
#pragma unroll
  for (int c = 0; c < 4; c++) {
    int g = base + tn + 16 * c;
    if (g < DM) {
      float b = __ldg(bias + g);
#pragma unroll
      for (int r = 0; r < 3; r++) {
        int m = tm + 32 * r;
        float v = sum2(acc[r][c]) + b;
        if (resid) v += resid[m * LDA + g];
        dst[m * LDA + g] = v;
      }
    }
  }
}

__device__ __forceinline__ void layernorm_rows(const float* __restrict__ src,
                                               float* __restrict__ dst,
                                               const float* __restrict__ g,
                                               const float* __restrict__ b) {
  const int tid = threadIdx.x;
  if (tid < MROWS) {
    const float* y = src + tid * LDA;
    float m = 0.f;
#pragma unroll 4
    for (int d = 0; d < DM; d++) m += y[d];
    m *= (1.0f / DM);
    float v = 0.f;
#pragma unroll 4
    for (int d = 0; d < DM; d++) { float t = y[d] - m; v = fmaf(t, t, v); }
    v *= (1.0f / DM);
    float inv = rsqrtf(v + 1e-5f);
    float* o = dst + tid * LDA;
#pragma unroll 4
    for (int d = 0; d < DM; d++)
      o[d] = (y[d] - m) * inv * __ldg(g + d) + __ldg(b + d);
  }
}

__global__ void __launch_bounds__(THREADS, 1)
geomapnet_kernel(const float* __restrict__ x,
                 const float* __restrict__ We, const float* __restrict__ be,
                 const float* __restrict__ pe,
                 const float* __restrict__ Wq, const float* __restrict__ bq,
                 const float* __restrict__ Wk, const float* __restrict__ bk,
                 const float* __restrict__ Wv, const float* __restrict__ bv,
                 const float* __restrict__ Wo, const float* __restrict__ bo,
                 const float* __restrict__ ln1g, const float* __restrict__ ln1b,
                 const float* __restrict__ W1, const float* __restrict__ b1,
                 const float* __restrict__ W2, const float* __restrict__ b2,
                 const float* __restrict__ ln2g, const float* __restrict__ ln2b,
                 const float* __restrict__ Wf, const float* __restrict__ bf,
                 float* __restrict__ out)
{
  extern __shared__ float smem[];
  float* sX = smem + OFF_X;
  float* sQ = smem + OFF_Q;
  float* sK = smem + OFF_K;
  float* sV = smem + OFF_V;
  float* b0f = smem + OFF_W0;   // ping buffer
  float* b1f = smem + OFF_W1;   // pong buffer (b0f..b0f+15232 contiguous)

  const int tid = threadIdx.x;
  const int rowbase = blockIdx.x * MROWS;

  // ---------- prologue: load x, stage We into combined buffer ----------
  for (int idx = tid; idx < MROWS * DIN; idx += THREADS) {
    int r = idx / DIN, c = idx - r * DIN;
    sQ[r * LDA + c] = x[(size_t)(rowbase + r) * DIN + c];
  }
  stage_w(b0f, WE_LDW, We, DIN, DM, DIN, 112);
  __syncthreads();

  // ---------- embedding: X = x @ We^T + be + pe ----------
  {
    ull acc[3][7];
    zero_acc<7>(acc);
    gemm_acc2<7>(sQ, LDA, b0f, WE_LDW, DIN, acc);
    const int tn = tid & 15, tm = tid >> 4;
#pragma unroll
    for (int c = 0; c < 7; c++) {
      int n = tn + 16 * c;
      if (n < DM) {
        float bias = __ldg(be + n);
#pragma unroll
        for (int r = 0; r < 3; r++) {
          int m = tm + 32 * r;
          sX[m * LDA + n] = sum2(acc[r][c]) + bias + __ldg(pe + (m % 3) * DM + n);
        }
      }
    }
  }
  __syncthreads();
  // stage Wq layer0 chunk0 -> b0
  stage_w(b0f, QK_LDW, Wq, DM, 64, DM, 64);
  __syncthreads();

  // ---------- encoder layers ----------
  for (int li = 0; li < NLAYERS; li++) {
    const float* Wq_i = Wq + li * DM * DM;
    const float* Wk_i = Wk + li * DM * DM;
    const float* Wv_i = Wv + li * DM * DM;
    const float* Wo_i = Wo + li * DM * DM;

    // Q c0 (b0) | stage Wq c1 -> b1
    { ull a[3][4]; zero_acc<4>(a); gemm_acc2<4>(sX, LDA, b0f, QK_LDW, DM, a);
      epi4(a, 0, bq + li * DM, sQ, nullptr);
      stage_w(b1f, QK_LDW, Wq_i + 64 * DM, DM, 36, DM, 64); }
    __syncthreads();
    // Q c1 (b1) | stage Wk c0 -> b0
    { ull a[3][4]; zero_acc<4>(a); gemm_acc2<4>(sX, LDA, b1f, QK_LDW, DM, a);
      epi4(a, 64, bq + li * DM, sQ, nullptr);
      stage_w(b0f, QK_LDW, Wk_i, DM, 64, DM, 64); }
    __syncthreads();
    // K c0 (b0) | stage Wk c1 -> b1
    { ull a[3][4]; zero_acc<4>(a); gemm_acc2<4>(sX, LDA, b0f, QK_LDW, DM, a);
      epi4(a, 0, bk + li * DM, sK, nullptr);
      stage_w(b1f, QK_LDW, Wk_i + 64 * DM, DM, 36, DM, 64); }
    __syncthreads();
    // K c1 (b1) | stage Wv c0 -> b0
    { ull a[3][4]; zero_acc<4>(a); gemm_acc2<4>(sX, LDA, b1f, QK_LDW, DM, a);
      epi4(a, 64, bk + li * DM, sK, nullptr);
      stage_w(b0f, QK_LDW, Wv_i, DM, 64, DM, 64); }
    __syncthreads();
    // V c0 (b0) | stage Wv c1 -> b1
    { ull a[3][4]; zero_acc<4>(a); gemm_acc2<4>(sX, LDA, b0f, QK_LDW, DM, a);
      epi4(a, 0, bv + li * DM, sV, nullptr);
      stage_w(b1f, QK_LDW, Wv_i + 64 * DM, DM, 36, DM, 64); }
    __syncthreads();
    // V c1 (b1) | stage Wo c0 -> b0
    { ull a[3][4]; zero_acc<4>(a); gemm_acc2<4>(sX, LDA, b1f, QK_LDW, DM, a);
      epi4(a, 64, bv + li * DM, sV, nullptr);
      stage_w(b0f, QK_LDW, Wo_i, DM, 64, DM, 64); }
    __syncthreads();

    // attention op | stage Wo c1 -> b1
    if (tid < TB * 10) {
      int e = tid / 10, h = tid - e * 10;
      const int base = h * 30;
      const float* Qe = sQ + (3 * e) * LDA;
      const float* Ke = sK + (3 * e) * LDA;
      const float* Ve = sV + (3 * e) * LDA;
      auto offf = [&](int f) { int s = f / 100; return s * LDA + (f - s * 100); };
      const float scale = 0.3162277660168379f;
      float att[3][3], q[30];
#pragma unroll
      for (int j = 0; j < 30; j++) q[j] = Qe[offf(base + j)];
#pragma unroll
      for (int b2_ = 0; b2_ < 3; b2_++) {
        float kk[10];
#pragma unroll
        for (int d3 = 0; d3 < 10; d3++) kk[d3] = Ke[offf(base + b2_ * 10 + d3)];
#pragma unroll
        for (int a2 = 0; a2 < 3; a2++) {
          float s2 = 0.f;
#pragma unroll
          for (int d3 = 0; d3 < 10; d3++) s2 = fmaf(q[a2 * 10 + d3], kk[d3], s2);
          att[a2][b2_] = s2 * scale;
        }
      }
#pragma unroll
      for (int a2 = 0; a2 < 3; a2++) {
        float mx = fmaxf(att[a2][0], fmaxf(att[a2][1], att[a2][2]));
        float sum = 0.f;
#pragma unroll
        for (int b2_ = 0; b2_ < 3; b2_++) { att[a2][b2_] = __expf(att[a2][b2_] - mx); sum += att[a2][b2_]; }
        float inv = 1.f / sum;
#pragma unroll
        for (int b2_ = 0; b2_ < 3; b2_++) att[a2][b2_] *= inv;
      }
      float* Qw = sQ + (3 * e) * LDA;
#pragma unroll
      for (int d3 = 0; d3 < 10; d3++) {
        float v0 = Ve[offf(base + d3)], v1 = Ve[offf(base + 10 + d3)], v2 = Ve[offf(base + 20 + d3)];
#pragma unroll
        for (int a2 = 0; a2 < 3; a2++)
          Qw[offf(base + a2 * 10 + d3)] = att[a2][0] * v0 + att[a2][1] * v1 + att[a2][2] * v2;
      }
    }
    stage_w(b1f, QK_LDW, Wo_i + 64 * DM, DM, 36, DM, 64);
    __syncthreads();

    // O c0 (b0) -> sK (+resid sX)
    { ull a[3][4]; zero_acc<4>(a); gemm_acc2<4>(sQ, LDA, b0f, QK_LDW, DM, a);
      epi4(a, 0, bo + li * DM, sK, sX); }
    __syncthreads();
    // O c1 (b1) | stage W1_0 -> b0
    { ull a[3][4]; zero_acc<4>(a); gemm_acc2<4>(sQ, LDA, b1f, QK_LDW, DM, a);
      epi4(a, 64, bo + li * DM, sK, sX);
      stage_w(b0f, QK_LDW, W1 + (size_t)li * FFD * DM, DM, 64, DM, 64); }
    __syncthreads();
    // LN1 -> sX
    layernorm_rows(sK, sX, ln1g + li * DM, ln1b + li * DM);
    __syncthreads();

    // ---- FFN: 8 chunks of 64 hidden, yacc accumulates across chunks ----
    ull yacc[3][7];
    zero_acc<7>(yacc);
    for (int cc = 0; cc < FFD / 64; cc++) {
      // F1_c (b0): hidden = relu(X @ W1c^T + b1c) -> sV | stage W2_c -> b1
      { ull h[3][4]; zero_acc<4>(h); gemm_acc2<4>(sX, LDA, b0f, QK_LDW, DM, h);
        const float* b1c = b1 + li * FFD + cc * 64;
        const int tn = tid & 15, tm = tid >> 4;
#pragma unroll
        for (int c = 0; c < 4; c++) {
          int n = tn + 16 * c;
          float bias = __ldg(b1c + n);
#pragma unroll
          for (int r = 0; r < 3; r++)
            sV[(tm + 32 * r) * LDA + n] = fmaxf(sum2(h[r][c]) + bias, 0.f);
        }
        stage_w(b1f, W2_LDW, W2 + (size_t)li * DM * FFD + cc * 64, FFD, DM, 64, 112); }
      __syncthreads();
      // F2_c (b1): yacc += hidden @ W2c^T | stage W1_{c+1} or layer-end targets
      gemm_acc2<7>(sV, LDA, b1f, W2_LDW, 64, yacc);
      if (cc < 7) {
        stage_w(b0f, QK_LDW, W1 + (size_t)li * FFD * DM + (cc + 1) * 64 * DM, DM, 64, DM, 64);
      } else {
        // final epilogue: sK = yacc + b2 + sX
        const float* b2i = b2 + li * DM;
        const int tn = tid & 15, tm = tid >> 4;
#pragma unroll
        for (int c = 0; c < 7; c++) {
          int n = tn + 16 * c;
          if (n < DM) {
            float bias = __ldg(b2i + n);
#pragma unroll
            for (int r = 0; r < 3; r++) {
              int m = tm + 32 * r;
              sK[m * LDA + n] = sum2(yacc[r][c]) + bias + sX[m * LDA + n];
            }
          }
        }
        if (li < NLAYERS - 1)
          stage_w(b0f, QK_LDW, Wq + (li + 1) * DM * DM, DM, 64, DM, 64);
      }
      __syncthreads();
    }

    // LN2 -> sX | last layer: stage Wf into combined region
    layernorm_rows(sK, sX, ln2g + li * DM, ln2b + li * DM);
    if (li == NLAYERS - 1)
      stage_w(b0f, WF_LDW, Wf, SD, NCLS, SD, NCLS);
    __syncthreads();
  }

  // ---------- classifier ----------
  for (int task = tid; task < TB * NCLS; task += THREADS) {
    int e = task / NCLS, c = task - e * NCLS;
    const float* Xe = sX + 3 * e * LDA;
    const float* wr = b0f + c * WF_LDW;
    ull acc = 0ull;
#pragma unroll
    for (int s = 0; s < 3; s++) {
#pragma unroll 5
      for (int d = 0; d < DM; d += 2) {
        ffma2(acc, pack2(Xe[s * LDA + d], Xe[s * LDA + d + 1]),
                   pack2(wr[s * DM + d], wr[s * DM + d + 1]));
      }
    }
    out[(size_t)(blockIdx.x * TB + e) * NCLS + c] = sum2(acc) + __ldg(bf + c);
  }
}

extern "C" void kernel_launch(void* const* d_in, const int* in_sizes, int n_in,
                              void* d_out, int out_size) {
  const float* x   = (const float*)d_in[0];
  const float* We  = (const float*)d_in[3];
  const float* be  = (const float*)d_in[4];
  const float* pe  = (const float*)d_in[5];
  const float* Wq  = (const float*)d_in[6];
  const float* bq  = (const float*)d_in[7];
  const float* Wk  = (const float*)d_in[8];
  const float* bk  = (const float*)d_in[9];
  const float* Wv  = (const float*)d_in[10];
  const float* bv  = (const float*)d_in[11];
  const float* Wo  = (const float*)d_in[12];
  const float* bo  = (const float*)d_in[13];
  const float* l1g = (const float*)d_in[14];
  const float* l1b = (const float*)d_in[15];
  const float* W1  = (const float*)d_in[16];
  const float* b1  = (const float*)d_in[17];
  const float* W2  = (const float*)d_in[18];
  const float* b2  = (const float*)d_in[19];
  const float* l2g = (const float*)d_in[20];
  const float* l2b = (const float*)d_in[21];
  const float* Wf  = (const float*)d_in[22];
  const float* bf  = (const float*)d_in[23];
  float* out = (float*)d_out;

  int Bsz = in_sizes[0] / (3 * DIN);       // 65536
  int nblocks = Bsz / TB;                  // 2048
  size_t smem = (size_t)SMEM_FLOATS * sizeof(float);  // 220,672 B

  cudaFuncSetAttribute(geomapnet_kernel,
                       cudaFuncAttributeMaxDynamicSharedMemorySize, (int)smem);
  geomapnet_kernel<<<nblocks, THREADS, smem>>>(x, We, be, pe, Wq, bq, Wk, bk, Wv, bv,
                                               Wo, bo, l1g, l1b, W1, b1, W2, b2,
                                               l2g, l2b, Wf, bf, out);
}

// round 7
// speedup vs baseline: 1.0349x; 1.0320x over previous
#include <cuda_runtime.h>

#define THREADS 256
#define TB 32
#define MROWS 96
#define LDA 104
#define LDWT 104
#define DM 100
#define DIN 72
#define FFD 512
#define NLAYERS 8
#define NCLS 40

// smem float offsets
#define SX 0
#define SQ 9984
#define SK 19968
#define SV 29952
#define SWT 39936
#define SMEM_FLOATS 50784   // 203,136 bytes (WT 104*104 + 32 pad)

typedef unsigned long long ull;

__device__ __forceinline__ void ffma2(ull& acc, ull a, ull b) {
  asm("fma.rn.f32x2 %0, %1, %2, %0;" : "+l"(acc) : "l"(a), "l"(b));
}
__device__ __forceinline__ ull pack2(float x, float y) {
  ull r; asm("mov.b64 %0, {%1, %2};" : "=l"(r) : "f"(x), "f"(y)); return r;
}
__device__ __forceinline__ void upk2(ull v, float& lo, float& hi) {
  asm("mov.b64 {%0, %1}, %2;" : "=f"(lo), "=f"(hi) : "l"(v));
}

// Stage W transposed: Wt[k][n] = (n < nvalid) ? src[n*sstride + k] : 0, k < K (mult of 4).
__device__ __forceinline__ void stage_wt(float* wt, const float* __restrict__ src,
                                         int sstride, int nvalid, int K) {
  const int total = (K >> 2) * 104;
  for (int idx = threadIdx.x; idx < total; idx += THREADS) {
    int kc = idx / 104;
    int n = idx - kc * 104;
    float4 v = make_float4(0.f, 0.f, 0.f, 0.f);
    if (n < nvalid) v = *reinterpret_cast<const float4*>(src + n * sstride + 4 * kc);
    int kb = 4 * kc;
    wt[(kb + 0) * LDWT + n] = v.x;
    wt[(kb + 1) * LDWT + n] = v.y;
    wt[(kb + 2) * LDWT + n] = v.z;
    wt[(kb + 3) * LDWT + n] = v.w;
  }
}

// C[m][n] += sum_k A[m][k] * Wt[k][n]
// thread (tm,tn): rows {tm+16r}, cols {4tn..4tn+3} u {52+4tn..52+4tn+3}
// acc[r][0..1] = col pairs of block1, acc[r][2..3] = block2. (f32x2 packs col pairs)
__device__ __forceinline__ void gemm_cp(const float* __restrict__ A,
                                        const float* __restrict__ Wt,
                                        int K, ull (&acc)[6][4], int tm, int tn) {
  const float* a0 = A + tm * LDA;
  const int c0 = 4 * tn, c1 = 52 + 4 * tn;
#pragma unroll 2
  for (int k = 0; k < K; k += 4) {
    float4 a[6];
#pragma unroll
    for (int r = 0; r < 6; r++)
      a[r] = *reinterpret_cast<const float4*>(a0 + (16 * r) * LDA + k);
#pragma unroll
    for (int kk = 0; kk < 4; kk++) {
      const float* wrow = Wt + (k + kk) * LDWT;
      float4 w0 = *reinterpret_cast<const float4*>(wrow + c0);
      float4 w1 = *reinterpret_cast<const float4*>(wrow + c1);
      ull w00 = pack2(w0.x, w0.y), w01 = pack2(w0.z, w0.w);
      ull w10 = pack2(w1.x, w1.y), w11 = pack2(w1.z, w1.w);
#pragma unroll
      for (int r = 0; r < 6; r++) {
        float av = (kk == 0) ? a[r].x : (kk == 1) ? a[r].y : (kk == 2) ? a[r].z : a[r].w;
        ull aa = pack2(av, av);
        ffma2(acc[r][0], aa, w00);
        ffma2(acc[r][1], aa, w01);
        ffma2(acc[r][2], aa, w10);
        ffma2(acc[r][3], aa, w11);
      }
    }
  }
}

__device__ __forceinline__ void zacc(ull (&acc)[6][4]) {
#pragma unroll
  for (int r = 0; r < 6; r++)
#pragma unroll
    for (int c = 0; c < 4; c++) acc[r][c] = 0ull;
}

// epilogue: dst[row][col] = acc + bias (+resid) (relu optional). Junk cols (>=100) land
// in LDA padding, never read. bias guarded by bmax for block2.
__device__ __forceinline__ void epi_cp(ull (&acc)[6][4], const float* __restrict__ bias,
                                       int bmax, float* __restrict__ dst,
                                       const float* __restrict__ resid, bool dorelu,
                                       int tm, int tn) {
  if (tn >= 13) return;
  const int c0 = 4 * tn, c1 = 52 + 4 * tn;
  float4 b0, b1;
  b0.x = __ldg(bias + c0); b0.y = __ldg(bias + c0 + 1);
  b0.z = __ldg(bias + c0 + 2); b0.w = __ldg(bias + c0 + 3);
  b1.x = (c1 + 0 < bmax) ? __ldg(bias + c1 + 0) : 0.f;
  b1.y = (c1 + 1 < bmax) ? __ldg(bias + c1 + 1) : 0.f;
  b1.z = (c1 + 2 < bmax) ? __ldg(bias + c1 + 2) : 0.f;
  b1.w = (c1 + 3 < bmax) ? __ldg(bias + c1 + 3) : 0.f;
#pragma unroll
  for (int r = 0; r < 6; r++) {
    int row = tm + 16 * r;
    float4 v0, v1;
    upk2(acc[r][0], v0.x, v0.y); upk2(acc[r][1], v0.z, v0.w);
    upk2(acc[r][2], v1.x, v1.y); upk2(acc[r][3], v1.z, v1.w);
    v0.x += b0.x; v0.y += b0.y; v0.z += b0.z; v0.w += b0.w;
    v1.x += b1.x; v1.y += b1.y; v1.z += b1.z; v1.w += b1.w;
    if (resid) {
      float4 r0 = *reinterpret_cast<const float4*>(resid + row * LDA + c0);
      float4 r1 = *reinterpret_cast<const float4*>(resid + row * LDA + c1);
      v0.x += r0.x; v0.y += r0.y; v0.z += r0.z; v0.w += r0.w;
      v1.x += r1.x; v1.y += r1.y; v1.z += r1.z; v1.w += r1.w;
    }
    if (dorelu) {
      v0.x = fmaxf(v0.x, 0.f); v0.y = fmaxf(v0.y, 0.f);
      v0.z = fmaxf(v0.z, 0.f); v0.w = fmaxf(v0.w, 0.f);
      v1.x = fmaxf(v1.x, 0.f); v1.y = fmaxf(v1.y, 0.f);
      v1.z = fmaxf(v1.z, 0.f); v1.w = fmaxf(v1.w, 0.f);
    }
    *reinterpret_cast<float4*>(dst + row * LDA + c0) = v0;
    *reinterpret_cast<float4*>(dst + row * LDA + c1) = v1;
  }
}

__device__ __forceinline__ void layernorm_rows(const float* __restrict__ src,
                                               float* __restrict__ dst,
                                               const float* __restrict__ g,
                                               const float* __restrict__ b) {
  const int tid = threadIdx.x;
  if (tid < MROWS) {
    const float* y = src + tid * LDA;
    float m = 0.f;
#pragma unroll 4
    for (int d = 0; d < DM; d++) m += y[d];
    m *= (1.0f / DM);
    float v = 0.f;
#pragma unroll 4
    for (int d = 0; d < DM; d++) { float t = y[d] - m; v = fmaf(t, t, v); }
    v *= (1.0f / DM);
    float inv = rsqrtf(v + 1e-5f);
    float* o = dst + tid * LDA;
#pragma unroll 4
    for (int d = 0; d < DM; d++)
      o[d] = (y[d] - m) * inv * __ldg(g + d) + __ldg(b + d);
  }
}

__global__ void __launch_bounds__(THREADS, 1)
geomapnet_kernel(const float* __restrict__ x,
                 const float* __restrict__ We, const float* __restrict__ be,
                 const float* __restrict__ pe,
                 const float* __restrict__ Wq, const float* __restrict__ bq,
                 const float* __restrict__ Wk, const float* __restrict__ bk,
                 const float* __restrict__ Wv, const float* __restrict__ bv,
                 const float* __restrict__ Wo, const float* __restrict__ bo,
                 const float* __restrict__ ln1g, const float* __restrict__ ln1b,
                 const float* __restrict__ W1, const float* __restrict__ b1,
                 const float* __restrict__ W2, const float* __restrict__ b2,
                 const float* __restrict__ ln2g, const float* __restrict__ ln2b,
                 const float* __restrict__ Wf, const float* __restrict__ bf,
                 float* __restrict__ out)
{
  extern __shared__ float sm[];
  float* sX = sm + SX;
  float* sQ = sm + SQ;
  float* sK = sm + SK;
  float* sV = sm + SV;
  float* wt = sm + SWT;

  const int tid = threadIdx.x;
  const int tn = tid & 15, tm = tid >> 4;
  const int rowbase = blockIdx.x * MROWS;

  // ---- load x -> sQ[96][0..71], stage We^T ----
  for (int idx = tid; idx < MROWS * (DIN / 4); idx += THREADS) {
    int r = idx / (DIN / 4), c4 = idx - r * (DIN / 4);
    *reinterpret_cast<float4*>(sQ + r * LDA + 4 * c4) =
        *reinterpret_cast<const float4*>(x + (size_t)(rowbase + r) * DIN + 4 * c4);
  }
  stage_wt(wt, We, DIN, DM, DIN);
  __syncthreads();

  // ---- embedding: X = x @ We^T + be + pe ----
  {
    ull acc[6][4]; zacc(acc);
    gemm_cp(sQ, wt, DIN, acc, tm, tn);
    if (tn < 13) {
      const int c0 = 4 * tn, c1 = 52 + 4 * tn;
#pragma unroll
      for (int r = 0; r < 6; r++) {
        int row = tm + 16 * r;
        int prow = (row % 3) * DM;
        float4 v0, v1;
        upk2(acc[r][0], v0.x, v0.y); upk2(acc[r][1], v0.z, v0.w);
        upk2(acc[r][2], v1.x, v1.y); upk2(acc[r][3], v1.z, v1.w);
        v0.x += __ldg(be + c0) + __ldg(pe + prow + c0);
        v0.y += __ldg(be + c0 + 1) + __ldg(pe + prow + c0 + 1);
        v0.z += __ldg(be + c0 + 2) + __ldg(pe + prow + c0 + 2);
        v0.w += __ldg(be + c0 + 3) + __ldg(pe + prow + c0 + 3);
        if (c1 + 0 < DM) v1.x += __ldg(be + c1) + __ldg(pe + prow + c1);
        if (c1 + 1 < DM) v1.y += __ldg(be + c1 + 1) + __ldg(pe + prow + c1 + 1);
        if (c1 + 2 < DM) v1.z += __ldg(be + c1 + 2) + __ldg(pe + prow + c1 + 2);
        if (c1 + 3 < DM) v1.w += __ldg(be + c1 + 3) + __ldg(pe + prow + c1 + 3);
        *reinterpret_cast<float4*>(sX + row * LDA + c0) = v0;
        *reinterpret_cast<float4*>(sX + row * LDA + c1) = v1;
      }
    }
  }
  __syncthreads();
  stage_wt(wt, Wq, DM, DM, DM);
  __syncthreads();

  // ---- encoder layers ----
  for (int li = 0; li < NLAYERS; li++) {
    // Q (wt = WqT already staged)
    { ull a[6][4]; zacc(a); gemm_cp(sX, wt, DM, a, tm, tn);
      epi_cp(a, bq + li * DM, DM, sQ, nullptr, false, tm, tn); }
    __syncthreads();
    stage_wt(wt, Wk + li * DM * DM, DM, DM, DM);
    __syncthreads();
    { ull a[6][4]; zacc(a); gemm_cp(sX, wt, DM, a, tm, tn);
      epi_cp(a, bk + li * DM, DM, sK, nullptr, false, tm, tn); }
    __syncthreads();
    stage_wt(wt, Wv + li * DM * DM, DM, DM, DM);
    __syncthreads();
    { ull a[6][4]; zacc(a); gemm_cp(sX, wt, DM, a, tm, tn);
      epi_cp(a, bv + li * DM, DM, sV, nullptr, false, tm, tn); }
    __syncthreads();

    // attention (flat row-major head split) + overlap stage WoT
    for (int task = tid; task < TB * 10; task += THREADS) {
      int e = task / 10, h = task - e * 10;
      const int base = h * 30;
      const float* Qe = sQ + (3 * e) * LDA;
      const float* Ke = sK + (3 * e) * LDA;
      const float* Ve = sV + (3 * e) * LDA;
      auto offf = [&](int f) { int s = f / 100; return s * LDA + (f - s * 100); };
      const float scale = 0.3162277660168379f;
      float att[3][3], q[30];
#pragma unroll
      for (int j = 0; j < 30; j++) q[j] = Qe[offf(base + j)];
#pragma unroll
      for (int b2_ = 0; b2_ < 3; b2_++) {
        float kk[10];
#pragma unroll
        for (int d3 = 0; d3 < 10; d3++) kk[d3] = Ke[offf(base + b2_ * 10 + d3)];
#pragma unroll
        for (int a2 = 0; a2 < 3; a2++) {
          float s2 = 0.f;
#pragma unroll
          for (int d3 = 0; d3 < 10; d3++) s2 = fmaf(q[a2 * 10 + d3], kk[d3], s2);
          att[a2][b2_] = s2 * scale;
        }
      }
#pragma unroll
      for (int a2 = 0; a2 < 3; a2++) {
        float mx = fmaxf(att[a2][0], fmaxf(att[a2][1], att[a2][2]));
        float sum = 0.f;
#pragma unroll
        for (int b2_ = 0; b2_ < 3; b2_++) { att[a2][b2_] = __expf(att[a2][b2_] - mx); sum += att[a2][b2_]; }
        float inv = 1.f / sum;
#pragma unroll
        for (int b2_ = 0; b2_ < 3; b2_++) att[a2][b2_] *= inv;
      }
      float* Qw = sQ + (3 * e) * LDA;
#pragma unroll
      for (int d3 = 0; d3 < 10; d3++) {
        float v0 = Ve[offf(base + d3)], v1 = Ve[offf(base + 10 + d3)], v2 = Ve[offf(base + 20 + d3)];
#pragma unroll
        for (int a2 = 0; a2 < 3; a2++)
          Qw[offf(base + a2 * 10 + d3)] = att[a2][0] * v0 + att[a2][1] * v1 + att[a2][2] * v2;
      }
    }
    stage_wt(wt, Wo + li * DM * DM, DM, DM, DM);
    __syncthreads();

    // O projection + residual -> sK
    { ull a[6][4]; zacc(a); gemm_cp(sQ, wt, DM, a, tm, tn);
      epi_cp(a, bo + li * DM, DM, sK, sX, false, tm, tn); }
    __syncthreads();
    // LN1 -> sX, overlap stage W1 chunk0
    layernorm_rows(sK, sX, ln1g + li * DM, ln1b + li * DM);
    stage_wt(wt, W1 + (size_t)li * FFD * DM, DM, 104, DM);
    __syncthreads();

    // ---- FFN: chunks of 104 hidden (last 96); yacc persists ----
    ull yacc[6][4]; zacc(yacc);
    int h0 = 0;
    for (int cc = 0; cc < 5; cc++) {
      int w = (cc < 4) ? 104 : 96;
      // hidden chunk = relu(X @ W1c^T + b1c) -> sV
      { ull f[6][4]; zacc(f); gemm_cp(sX, wt, DM, f, tm, tn);
        epi_cp(f, b1 + li * FFD + h0, w, sV, nullptr, true, tm, tn); }
      __syncthreads();
      // stage W2 chunk (k-rows = hidden slice)
      stage_wt(wt, W2 + (size_t)li * DM * FFD + h0, FFD, DM, w);
      __syncthreads();
      gemm_cp(sV, wt, w, yacc, tm, tn);
      __syncthreads();
      if (cc < 4) {
        int nh0 = h0 + 104;
        int nw = (cc < 3) ? 104 : 96;
        stage_wt(wt, W1 + (size_t)li * FFD * DM + (size_t)nh0 * DM, DM, nw, DM);
        __syncthreads();
      }
      h0 += w;
    }
    // final FFN epilogue + residual -> sK
    epi_cp(yacc, b2 + li * DM, DM, sK, sX, false, tm, tn);
    __syncthreads();
    // LN2 -> sX, overlap stage next layer's WqT
    layernorm_rows(sK, sX, ln2g + li * DM, ln2b + li * DM);
    if (li < NLAYERS - 1)
      stage_wt(wt, Wq + (li + 1) * DM * DM, DM, DM, DM);
    __syncthreads();
  }

  // ---- classifier: out = flat(X)[300] @ Wf^T + bf (Wf from L2) ----
  for (int task = tid; task < TB * NCLS; task += THREADS) {
    int e = task / NCLS, c = task - e * NCLS;
    const float* Xe = sX + 3 * e * LDA;
    const float* wr = Wf + c * 300;
    float dot = __ldg(bf + c);
#pragma unroll
    for (int s = 0; s < 3; s++) {
      const float* xs = Xe + s * LDA;
      const float* ws = wr + s * DM;
#pragma unroll 5
      for (int d = 0; d < DM; d += 4) {
        float4 xv = *reinterpret_cast<const float4*>(xs + d);
        float4 wv = *reinterpret_cast<const float4*>(ws + d);
        dot = fmaf(xv.x, wv.x, dot); dot = fmaf(xv.y, wv.y, dot);
        dot = fmaf(xv.z, wv.z, dot); dot = fmaf(xv.w, wv.w, dot);
      }
    }
    out[(size_t)(blockIdx.x * TB + e) * NCLS + c] = dot;
  }
}

extern "C" void kernel_launch(void* const* d_in, const int* in_sizes, int n_in,
                              void* d_out, int out_size) {
  const float* x   = (const float*)d_in[0];
  const float* We  = (const float*)d_in[3];
  const float* be  = (const float*)d_in[4];
  const float* pe  = (const float*)d_in[5];
  const float* Wq  = (const float*)d_in[6];
  const float* bq  = (const float*)d_in[7];
  const float* Wk  = (const float*)d_in[8];
  const float* bk  = (const float*)d_in[9];
  const float* Wv  = (const float*)d_in[10];
  const float* bv  = (const float*)d_in[11];
  const float* Wo  = (const float*)d_in[12];
  const float* bo  = (const float*)d_in[13];
  const float* l1g = (const float*)d_in[14];
  const float* l1b = (const float*)d_in[15];
  const float* W1  = (const float*)d_in[16];
  const float* b1  = (const float*)d_in[17];
  const float* W2  = (const float*)d_in[18];
  const float* b2  = (const float*)d_in[19];
  const float* l2g = (const float*)d_in[20];
  const float* l2b = (const float*)d_in[21];
  const float* Wf  = (const float*)d_in[22];
  const float* bf  = (const float*)d_in[23];
  float* out = (float*)d_out;

  int Bsz = in_sizes[0] / (3 * DIN);       // 65536
  int nblocks = Bsz / TB;                  // 2048
  size_t smem = (size_t)SMEM_FLOATS * sizeof(float);  // 203,136 B

  cudaFuncSetAttribute(geomapnet_kernel,
                       cudaFuncAttributeMaxDynamicSharedMemorySize, (int)smem);
  geomapnet_kernel<<<nblocks, THREADS, smem>>>(x, We, be, pe, Wq, bq, Wk, bk, Wv, bv,
                                               Wo, bo, l1g, l1b, W1, b1, W2, b2,
                                               l2g, l2b, Wf, bf, out);
}